// round 13
// baseline (speedup 1.0000x reference)
#include <cuda_runtime.h>
#include <cstdint>
#include <cstddef>

#define XWID  14
#define XPAD  16
#define PROJ  128
#define DM    512
#define LAT   256
#define BB    64
#define SS    512
#define NCW   6
#define INW   768

// ------------- smem layout (float offsets) -------------
#define SM_WHR   0        // [j<64][dout<128]      8192
#define SM_BASE  8192     // [b<4][256]            1024
#define SM_H     9216     // [b<4][128]            512
#define SM_RECV  9728     // [src8][b<4][16]       512
#define SM_GATE  10240    // [gt<4][b<4][64]       1024
#define SM_A     11264    // [b<4][64]             256
#define SM_CTX   11520    // [b<4][256]            1024
#define SM_BARS  12544    // 2 x u64 barriers      4
#define SM_X     12560    // [b<4][512][16]        32768
#define SM_TOT_FLOATS 45328
#define SM_TOT_BYTES  (SM_TOT_FLOATS * 4)

// history for head epilogue
__device__ __align__(16) float g_hs[(size_t)BB * SS * PROJ];

// ---------------- helpers ----------------
static __device__ __forceinline__ uint32_t su32(const void* p) {
    return (uint32_t)__cvta_generic_to_shared(p);
}
static __device__ __forceinline__ uint32_t mapa_rank(uint32_t a, uint32_t r) {
    uint32_t o;
    asm("mapa.shared::cluster.u32 %0, %1, %2;" : "=r"(o) : "r"(a), "r"(r));
    return o;
}
static __device__ __forceinline__ uint32_t ctarank() {
    uint32_t r;
    asm("mov.u32 %0, %%cluster_ctarank;" : "=r"(r));
    return r;
}
static __device__ __forceinline__ void cl_sync() {
    asm volatile("barrier.cluster.arrive.aligned;" ::: "memory");
    asm volatile("barrier.cluster.wait.aligned;" ::: "memory");
}
static __device__ __forceinline__ void mbar_init(uint32_t bar) {
    asm volatile("mbarrier.init.shared.b64 [%0], 1;" :: "r"(bar) : "memory");
}
static __device__ __forceinline__ void mbar_arm(uint32_t bar, uint32_t tx) {
    asm volatile("mbarrier.arrive.expect_tx.shared.b64 _, [%0], %1;"
                 :: "r"(bar), "r"(tx) : "memory");
}
static __device__ __forceinline__ void mbar_wait(uint32_t bar, uint32_t ph) {
    asm volatile(
        "{\n\t.reg .pred P;\n"
        "W%=:\n\t"
        "mbarrier.try_wait.parity.acquire.cluster.shared::cta.b64 P, [%0], %1;\n\t"
        "@!P bra W%=;\n\t}"
        :: "r"(bar), "r"(ph) : "memory");
}
static __device__ __forceinline__ void sta32(uint32_t addr, float v, uint32_t bar) {
    asm volatile(
        "st.async.shared::cluster.mbarrier::complete_tx::bytes.b32 [%0], %1, [%2];"
        :: "r"(addr), "r"(__float_as_uint(v)), "r"(bar) : "memory");
}
static __device__ __forceinline__ uint64_t pk(float lo, float hi) {
    uint64_t r;
    asm("mov.b64 %0, {%1, %2};" : "=l"(r) : "f"(lo), "f"(hi));
    return r;
}
static __device__ __forceinline__ void upk(uint64_t v, float& lo, float& hi) {
    asm("mov.b64 {%0, %1}, %2;" : "=f"(lo), "=f"(hi) : "l"(v));
}
static __device__ __forceinline__ void fma2(uint64_t& a, uint64_t b, uint64_t c) {
    asm("fma.rn.f32x2 %0, %1, %2, %0;" : "+l"(a) : "l"(b), "l"(c));
}
static __device__ __forceinline__ float ex2f(float x) {
    float r;
    asm("ex2.approx.f32 %0, %1;" : "=f"(r) : "f"(x));
    return r;
}
static __device__ __forceinline__ float rcpf(float x) {
    float r;
    asm("rcp.approx.f32 %0, %1;" : "=f"(r) : "f"(x));
    return r;
}
static __device__ __forceinline__ float fsig(float x) {
    return rcpf(1.0f + ex2f(-1.4426950408889634f * x));
}
static __device__ __forceinline__ float ftanh(float x) {
    return fmaf(-2.0f, rcpf(1.0f + ex2f(2.8853900817779268f * x)), 1.0f);
}
static __device__ __forceinline__ float warp_sum(float v) {
#pragma unroll
    for (int m = 16; m > 0; m >>= 1) v += __shfl_xor_sync(0xffffffffu, v, m);
    return v;
}

// =====================================================================
// Fused kernel: the EXACT R3 scan loop (2555.6us best) + LN/head
// epilogue after the final cluster sync. No other changes.
// 128 CTAs, cluster 8, 256 threads. Cluster cl handles batches
// [4cl, 4cl+4). Rank owns c-dims [64r,64r+64) and h-dims [16r,16r+16).
// =====================================================================
__global__ void __cluster_dims__(8, 1, 1) __launch_bounds__(256, 1)
fused_kernel(const float* __restrict__ x, const float* __restrict__ ctx,
             const float* __restrict__ cmdW, const float* __restrict__ cmdb,
             const float* __restrict__ coordW, const float* __restrict__ coordb,
             const float* __restrict__ W_ih, const float* __restrict__ W_hh,
             const float* __restrict__ bih, const float* __restrict__ bhh,
             const float* __restrict__ W_hr,
             const float* __restrict__ lng, const float* __restrict__ lnb,
             const float* __restrict__ ocW, const float* __restrict__ ocb,
             const float* __restrict__ oxW, const float* __restrict__ oxb,
             const float* __restrict__ scl, float* __restrict__ out)
{
    extern __shared__ float sm[];
    float* whr  = sm + SM_WHR;
    float* base = sm + SM_BASE;
    float* hbuf = sm + SM_H;
    float* recv = sm + SM_RECV;
    float* gbuf = sm + SM_GATE;
    float* abuf = sm + SM_A;
    float* ctxs = sm + SM_CTX;
    float* xs   = sm + SM_X;

    const int t = threadIdx.x;
    const uint32_t rank = ctarank();
    const int b4 = (blockIdx.x >> 3) * 4;
    const int gt = t >> 6, cl = t & 63;
    const int row = gt * 512 + (int)rank * 64 + cl;

    // --- W_hh row into packed registers (64 x u64 = 128 floats) ---
    uint64_t w2[64];
    {
        const ulonglong2* p = (const ulonglong2*)(W_hh + (size_t)row * PROJ);
#pragma unroll
        for (int q = 0; q < 32; q++) {
            ulonglong2 v = p[q];
            w2[2 * q] = v.x;
            w2[2 * q + 1] = v.y;
        }
    }

    // ---------------- prologue phase 1: small smem loads ----------------
    float* cw = xs;           // 3072
    float* qw = xs + 3072;    // 4096
    float* bs = xs + 7168;    // 512
    for (int i = t; i < DM * 6; i += 256) cw[i] = cmdW[i];
    for (int i = t; i < DM * 8; i += 256) qw[i] = coordW[i];
    for (int i = t; i < DM; i += 256) bs[i] = cmdb[i] + coordb[i];
    for (int i = t; i < 4 * LAT; i += 256) {
        int b = i >> 8, j = i & 255;
        ctxs[i] = ctx[(size_t)(b4 + b) * LAT + j];
    }
    for (int i = t; i < PROJ * 64; i += 256) {
        int d = i >> 6, j = i & 63;
        whr[j * 128 + d] = W_hr[(size_t)d * DM + rank * 64 + j];
    }
    for (int i = t; i < 512; i += 256) hbuf[i] = 0.0f;
    __syncthreads();

    // ---------------- phase 2: fold input weights + base ----------------
    float ac[XWID];
#pragma unroll
    for (int k = 0; k < XWID; k++) ac[k] = 0.0f;
    float gB = bih[row] + bhh[row];
    {
        const float4* wr = (const float4*)(W_ih + (size_t)row * INW);
        for (int d4 = 0; d4 < DM / 4; d4++) {
            float4 w4 = wr[d4];
            float wa[4] = {w4.x, w4.y, w4.z, w4.w};
#pragma unroll
            for (int u = 0; u < 4; u++) {
                int d = d4 * 4 + u;
                float wv = wa[u];
#pragma unroll
                for (int k = 0; k < 6; k++) ac[k] += wv * cw[d * 6 + k];
#pragma unroll
                for (int k = 0; k < 8; k++) ac[6 + k] += wv * qw[d * 8 + k];
                gB += wv * bs[d];
            }
        }
    }
    {
        float bb0 = 0, bb1 = 0, bb2 = 0, bb3 = 0;
        const float4* wc = (const float4*)(W_ih + (size_t)row * INW + DM);
#pragma unroll 4
        for (int q = 0; q < LAT / 4; q++) {
            float4 w = wc[q];
            int j = q * 4;
            bb0 += w.x * ctxs[j] + w.y * ctxs[j + 1] + w.z * ctxs[j + 2] + w.w * ctxs[j + 3];
            bb1 += w.x * ctxs[256 + j] + w.y * ctxs[256 + j + 1] + w.z * ctxs[256 + j + 2] + w.w * ctxs[256 + j + 3];
            bb2 += w.x * ctxs[512 + j] + w.y * ctxs[512 + j + 1] + w.z * ctxs[512 + j + 2] + w.w * ctxs[512 + j + 3];
            bb3 += w.x * ctxs[768 + j] + w.y * ctxs[768 + j + 1] + w.z * ctxs[768 + j + 2] + w.w * ctxs[768 + j + 3];
        }
        base[t] = gB + bb0;
        base[256 + t] = gB + bb1;
        base[512 + t] = gB + bb2;
        base[768 + t] = gB + bb3;
    }
    uint64_t ac2[8];
#pragma unroll
    for (int k = 0; k < 7; k++) ac2[k] = pk(ac[2 * k], ac[2 * k + 1]);
    ac2[7] = pk(0.0f, 0.0f);
    __syncthreads();

    // ---------------- phase 3: x load (padded stride 16) ----------------
    for (int i = t; i < 4 * SS * XPAD; i += 256) {
        int b = i >> 13;
        int rem = i & 8191;
        int s = rem >> 4, k = rem & 15;
        xs[i] = (k < XWID) ? x[((size_t)(b4 + b) * SS + s) * XWID + k] : 0.0f;
    }

    // ---------------- barriers + comm addresses ----------------
    const uint32_t barF = su32(sm + SM_BARS);       // partials -> owner
    const uint32_t barH = su32(sm + SM_BARS) + 8;   // h broadcast -> all
    if (t == 0) {
        mbar_init(barF);
        mbar_init(barH);
        mbar_arm(barF, 2048);
        mbar_arm(barH, 2048);
    }

    const int bh = t >> 7, dout = t & 127;
    const uint32_t ow = (uint32_t)(dout >> 4);
    const uint32_t pa0 = mapa_rank(su32(&recv[rank * 64 + (uint32_t)bh * 16 + (dout & 15)]), ow);
    const uint32_t pa1 = mapa_rank(su32(&recv[rank * 64 + (uint32_t)(bh + 2) * 16 + (dout & 15)]), ow);
    const uint32_t pfb = mapa_rank(barF, ow);

    const int ob = t >> 4, od = t & 15;             // owner roles (t<64)
    uint32_t hdst[8], hbb[8];
    if (t < 64) {
        uint32_t la = su32(&hbuf[ob * 128 + (int)rank * 16 + od]);
#pragma unroll
        for (uint32_t d = 0; d < 8; d++) {
            hdst[d] = mapa_rank(la, d);
            hbb[d] = mapa_rank(barH, d);
        }
    }
    const int cb = t >> 6, cj = t & 63;             // c-update roles
    float c_reg = 0.0f;
    __syncthreads();
    cl_sync();

    const ulonglong2* hp0 = (const ulonglong2*)(hbuf);
    const ulonglong2* hp1 = (const ulonglong2*)(hbuf + 128);
    const ulonglong2* hp2 = (const ulonglong2*)(hbuf + 256);
    const ulonglong2* hp3 = (const ulonglong2*)(hbuf + 384);

    // =================== main sequential loop (R3 verbatim) ============
    for (int s = 0; s < SS; s++) {
        // ---- gates: base + W_hh.h + AC.x ----
        uint64_t a0 = pk(base[t], 0.0f);
        uint64_t a1 = pk(base[256 + t], 0.0f);
        uint64_t a2 = pk(base[512 + t], 0.0f);
        uint64_t a3 = pk(base[768 + t], 0.0f);
#pragma unroll
        for (int q = 0; q < 32; q++) {
            ulonglong2 v0 = hp0[q], v1 = hp1[q], v2 = hp2[q], v3 = hp3[q];
            fma2(a0, w2[2 * q], v0.x); fma2(a0, w2[2 * q + 1], v0.y);
            fma2(a1, w2[2 * q], v1.x); fma2(a1, w2[2 * q + 1], v1.y);
            fma2(a2, w2[2 * q], v2.x); fma2(a2, w2[2 * q + 1], v2.y);
            fma2(a3, w2[2 * q], v3.x); fma2(a3, w2[2 * q + 1], v3.y);
        }
        {
            const ulonglong2* e0 = (const ulonglong2*)(xs + 0 * 8192 + s * XPAD);
            const ulonglong2* e1 = (const ulonglong2*)(xs + 1 * 8192 + s * XPAD);
            const ulonglong2* e2 = (const ulonglong2*)(xs + 2 * 8192 + s * XPAD);
            const ulonglong2* e3 = (const ulonglong2*)(xs + 3 * 8192 + s * XPAD);
#pragma unroll
            for (int q = 0; q < 4; q++) {
                ulonglong2 u0 = e0[q], u1 = e1[q], u2 = e2[q], u3 = e3[q];
                fma2(a0, ac2[2 * q], u0.x); fma2(a0, ac2[2 * q + 1], u0.y);
                fma2(a1, ac2[2 * q], u1.x); fma2(a1, ac2[2 * q + 1], u1.y);
                fma2(a2, ac2[2 * q], u2.x); fma2(a2, ac2[2 * q + 1], u2.y);
                fma2(a3, ac2[2 * q], u3.x); fma2(a3, ac2[2 * q + 1], u3.y);
            }
        }
        float lo, hi, g0, g1, g2, g3;
        upk(a0, lo, hi); g0 = lo + hi;
        upk(a1, lo, hi); g1 = lo + hi;
        upk(a2, lo, hi); g2 = lo + hi;
        upk(a3, lo, hi); g3 = lo + hi;
        if (gt == 2) { g0 = ftanh(g0); g1 = ftanh(g1); g2 = ftanh(g2); g3 = ftanh(g3); }
        else         { g0 = fsig(g0);  g1 = fsig(g1);  g2 = fsig(g2);  g3 = fsig(g3);  }
        gbuf[gt * 256 + 0 * 64 + cl] = g0;
        gbuf[gt * 256 + 1 * 64 + cl] = g1;
        gbuf[gt * 256 + 2 * 64 + cl] = g2;
        gbuf[gt * 256 + 3 * 64 + cl] = g3;
        __syncthreads();

        // ---- c update: a = o * tanh(c) ----
        {
            float gi = gbuf[0 * 256 + cb * 64 + cj];
            float gf = gbuf[1 * 256 + cb * 64 + cj];
            float gg = gbuf[2 * 256 + cb * 64 + cj];
            float gO = gbuf[3 * 256 + cb * 64 + cj];
            c_reg = gf * c_reg + gi * gg;
            abuf[cb * 64 + cj] = gO * ftanh(c_reg);
        }
        __syncthreads();

        // ---- projection partials (dout, batches bh, bh+2) ----
        float pe = 0.0f, po = 0.0f;
        {
            const float4* aqe = (const float4*)(abuf + bh * 64);
            const float4* aqo = (const float4*)(abuf + (bh + 2) * 64);
#pragma unroll
            for (int q = 0; q < 16; q++) {
                int j = q * 4;
                float4 va = aqe[q];
                float4 vb = aqo[q];
                float wv0 = whr[(j + 0) * 128 + dout];
                float wv1 = whr[(j + 1) * 128 + dout];
                float wv2 = whr[(j + 2) * 128 + dout];
                float wv3 = whr[(j + 3) * 128 + dout];
                pe += va.x * wv0 + va.y * wv1 + va.z * wv2 + va.w * wv3;
                po += vb.x * wv0 + vb.y * wv1 + vb.z * wv2 + vb.w * wv3;
            }
        }
        sta32(pa0, pe, pfb);
        sta32(pa1, po, pfb);

        // ---- owners (warps 0-1): reduce 8 partials + broadcast ----
        if (t < 64) {
            mbar_wait(barF, (uint32_t)s & 1u);
            if (t == 0) mbar_arm(barF, 2048);
            float hv = recv[t] + recv[64 + t] + recv[128 + t] + recv[192 + t]
                     + recv[256 + t] + recv[320 + t] + recv[384 + t] + recv[448 + t];
#pragma unroll
            for (int d = 0; d < 8; d++) sta32(hdst[d], hv, hbb[d]);
            g_hs[((size_t)(b4 + ob) * SS + s) * PROJ + (int)rank * 16 + od] = hv;
        }

        // ---- everyone: wait for next h ----
        mbar_wait(barH, (uint32_t)s & 1u);
        if (t == 0) mbar_arm(barH, 2048);
    }
    cl_sync();   // release g_hs writes cluster-wide

    // =================== epilogue: LayerNorm + heads ===================
    {
        const size_t OUT_OFF = (size_t)BB * SS * NCW;
        const int lane = t & 31, wrp = t >> 5;
        const float scale = scl[0];
        const float4 lg = ((const float4*)lng)[lane];
        const float4 lb = ((const float4*)lnb)[lane];
        for (int ridx = wrp; ridx < 4 * SS; ridx += 8) {
            const int bl = ridx >> 9, sl = ridx & 511;
            const size_t rrow = (size_t)(b4 + bl) * SS + sl;
            const float4 h4 = ((const float4*)g_hs)[rrow * 32 + lane];
            float sum = h4.x + h4.y + h4.z + h4.w;
            sum = warp_sum(sum);
            float mu = sum * (1.0f / 128.0f);
            float dx = h4.x - mu, dy = h4.y - mu, dz = h4.z - mu, dw = h4.w - mu;
            float sq = dx * dx + dy * dy + dz * dz + dw * dw;
            sq = warp_sum(sq);
            float rs = rsqrtf(sq * (1.0f / 128.0f) + 1e-5f);
            float y0 = dx * rs * lg.x + lb.x;
            float y1 = dy * rs * lg.y + lb.y;
            float y2 = dz * rs * lg.z + lb.z;
            float y3 = dw * rs * lg.w + lb.w;

            float l0, l1, l2, l3, l4, l5;
#define DOLOGIT(m, dst)                                                         \
            {                                                                   \
                const float* wrow = ocW + (m) * PROJ + lane * 4;                \
                float p = y0 * wrow[0] + y1 * wrow[1] + y2 * wrow[2] + y3 * wrow[3]; \
                p = warp_sum(p);                                                \
                dst = p + ocb[m];                                               \
                if (lane == (m)) out[rrow * NCW + (m)] = dst;                   \
            }
            DOLOGIT(0, l0) DOLOGIT(1, l1) DOLOGIT(2, l2)
            DOLOGIT(3, l3) DOLOGIT(4, l4) DOLOGIT(5, l5)
#undef DOLOGIT
#define DOCOORD(m)                                                              \
            {                                                                   \
                const float* wrow = oxW + (m) * (PROJ + NCW) + lane * 4;        \
                float p = y0 * wrow[0] + y1 * wrow[1] + y2 * wrow[2] + y3 * wrow[3]; \
                p = warp_sum(p);                                                \
                const float* wt = oxW + (m) * (PROJ + NCW) + PROJ;              \
                float tot = p + l0 * wt[0] + l1 * wt[1] + l2 * wt[2] + l3 * wt[3] \
                              + l4 * wt[4] + l5 * wt[5] + oxb[m];               \
                float co = tanhf(tot * scale);                                  \
                if (lane == (m)) out[OUT_OFF + rrow * NCW + (m)] = co;          \
            }
            DOCOORD(0) DOCOORD(1) DOCOORD(2) DOCOORD(3) DOCOORD(4) DOCOORD(5)
#undef DOCOORD
        }
    }
}

// =====================================================================
extern "C" void kernel_launch(void* const* d_in, const int* in_sizes, int n_in,
                              void* d_out, int out_size)
{
    (void)in_sizes; (void)n_in; (void)out_size;
    const float* x           = (const float*)d_in[0];
    const float* context     = (const float*)d_in[1];
    const float* cmd_W       = (const float*)d_in[2];
    const float* cmd_b       = (const float*)d_in[3];
    const float* coord_W     = (const float*)d_in[4];
    const float* coord_b     = (const float*)d_in[5];
    const float* W_ih        = (const float*)d_in[6];
    const float* W_hh        = (const float*)d_in[7];
    const float* b_ih        = (const float*)d_in[8];
    const float* b_hh        = (const float*)d_in[9];
    const float* W_hr        = (const float*)d_in[10];
    const float* ln_g        = (const float*)d_in[11];
    const float* ln_b        = (const float*)d_in[12];
    const float* outc_W      = (const float*)d_in[13];
    const float* outc_b      = (const float*)d_in[14];
    const float* outx_W      = (const float*)d_in[15];
    const float* outx_b      = (const float*)d_in[16];
    const float* coord_scale = (const float*)d_in[17];
    float* out = (float*)d_out;

    cudaFuncSetAttribute(fused_kernel,
                         cudaFuncAttributeMaxDynamicSharedMemorySize,
                         SM_TOT_BYTES);

    fused_kernel<<<128, 256, SM_TOT_BYTES>>>(x, context, cmd_W, cmd_b,
                                             coord_W, coord_b, W_ih, W_hh,
                                             b_ih, b_hh, W_hr,
                                             ln_g, ln_b, outc_W, outc_b,
                                             outx_W, outx_b, coord_scale, out);
}

// round 14
// speedup vs baseline: 1.3844x; 1.3844x over previous
#include <cuda_runtime.h>
#include <cstdint>
#include <cstddef>

#define XWID  14
#define XPAD  16
#define PROJ  128
#define DM    512
#define LAT   256
#define BB    64
#define SS    512
#define NCW   6
#define INW   768

// ------------- smem layout (float offsets) -------------
#define SM_WHR   0        // [j<64][dout<128]      8192
#define SM_BASE  8192     // [b<4][256]            1024
#define SM_H     9216     // [b<4][128]            512
#define SM_RECV  9728     // [src8][b<4][16]       512
#define SM_GATE  10240    // [gt<4][b<4][64]       1024
#define SM_A     11264    // [b<4][64]             256
#define SM_CTX   11520    // [b<4][256]            1024
#define SM_BARS  12544    // 2 x u64 barriers      4
#define SM_X     12560    // [b<4][512][16]        32768
#define SM_TOT_FLOATS 45328
#define SM_TOT_BYTES  (SM_TOT_FLOATS * 4)

// history for head kernel
__device__ __align__(16) float g_hs[(size_t)BB * SS * PROJ];

// ---------------- helpers ----------------
static __device__ __forceinline__ uint32_t su32(const void* p) {
    return (uint32_t)__cvta_generic_to_shared(p);
}
static __device__ __forceinline__ uint32_t mapa_rank(uint32_t a, uint32_t r) {
    uint32_t o;
    asm("mapa.shared::cluster.u32 %0, %1, %2;" : "=r"(o) : "r"(a), "r"(r));
    return o;
}
static __device__ __forceinline__ uint32_t ctarank() {
    uint32_t r;
    asm("mov.u32 %0, %%cluster_ctarank;" : "=r"(r));
    return r;
}
static __device__ __forceinline__ void cl_sync() {
    asm volatile("barrier.cluster.arrive.aligned;" ::: "memory");
    asm volatile("barrier.cluster.wait.aligned;" ::: "memory");
}
static __device__ __forceinline__ void mbar_init(uint32_t bar) {
    asm volatile("mbarrier.init.shared.b64 [%0], 1;" :: "r"(bar) : "memory");
}
static __device__ __forceinline__ void mbar_arm(uint32_t bar, uint32_t tx) {
    asm volatile("mbarrier.arrive.expect_tx.shared.b64 _, [%0], %1;"
                 :: "r"(bar), "r"(tx) : "memory");
}
static __device__ __forceinline__ void mbar_wait(uint32_t bar, uint32_t ph) {
    asm volatile(
        "{\n\t.reg .pred P;\n"
        "W%=:\n\t"
        "mbarrier.try_wait.parity.acquire.cluster.shared::cta.b64 P, [%0], %1;\n\t"
        "@!P bra W%=;\n\t}"
        :: "r"(bar), "r"(ph) : "memory");
}
static __device__ __forceinline__ void sta32(uint32_t addr, float v, uint32_t bar) {
    asm volatile(
        "st.async.shared::cluster.mbarrier::complete_tx::bytes.b32 [%0], %1, [%2];"
        :: "r"(addr), "r"(__float_as_uint(v)), "r"(bar) : "memory");
}
static __device__ __forceinline__ uint64_t pk(float lo, float hi) {
    uint64_t r;
    asm("mov.b64 %0, {%1, %2};" : "=l"(r) : "f"(lo), "f"(hi));
    return r;
}
static __device__ __forceinline__ void upk(uint64_t v, float& lo, float& hi) {
    asm("mov.b64 {%0, %1}, %2;" : "=f"(lo), "=f"(hi) : "l"(v));
}
static __device__ __forceinline__ void fma2(uint64_t& a, uint64_t b, uint64_t c) {
    asm("fma.rn.f32x2 %0, %1, %2, %0;" : "+l"(a) : "l"(b), "l"(c));
}
static __device__ __forceinline__ float ex2f(float x) {
    float r;
    asm("ex2.approx.f32 %0, %1;" : "=f"(r) : "f"(x));
    return r;
}
static __device__ __forceinline__ float rcpf(float x) {
    float r;
    asm("rcp.approx.f32 %0, %1;" : "=f"(r) : "f"(x));
    return r;
}
static __device__ __forceinline__ float fsig(float x) {
    return rcpf(1.0f + ex2f(-1.4426950408889634f * x));
}
static __device__ __forceinline__ float ftanh(float x) {
    return fmaf(-2.0f, rcpf(1.0f + ex2f(2.8853900817779268f * x)), 1.0f);
}
static __device__ __forceinline__ float warp_sum(float v) {
#pragma unroll
    for (int m = 16; m > 0; m >>= 1) v += __shfl_xor_sync(0xffffffffu, v, m);
    return v;
}

// =====================================================================
// Scan kernel: two-kernel R3 champion with ONE change — the
// h-independent gate work (base + AC*x) is computed BEFORE waiting on
// the h broadcast, overlapping the owner round-trip (hoist validated
// in R9 at -113us even under adverse conditions).
// 128 CTAs, cluster 8, 256 threads. Cluster handles batches
// [4cl, 4cl+4). Rank owns c-dims [64r,64r+64) and h-dims [16r,16r+16).
// =====================================================================
__global__ void __cluster_dims__(8, 1, 1) __launch_bounds__(256, 1)
scan_kernel(const float* __restrict__ x, const float* __restrict__ ctx,
            const float* __restrict__ cmdW, const float* __restrict__ cmdb,
            const float* __restrict__ coordW, const float* __restrict__ coordb,
            const float* __restrict__ W_ih, const float* __restrict__ W_hh,
            const float* __restrict__ bih, const float* __restrict__ bhh,
            const float* __restrict__ W_hr)
{
    extern __shared__ float sm[];
    float* whr  = sm + SM_WHR;
    float* base = sm + SM_BASE;
    float* hbuf = sm + SM_H;
    float* recv = sm + SM_RECV;
    float* gbuf = sm + SM_GATE;
    float* abuf = sm + SM_A;
    float* ctxs = sm + SM_CTX;
    float* xs   = sm + SM_X;

    const int t = threadIdx.x;
    const uint32_t rank = ctarank();
    const int b4 = (blockIdx.x >> 3) * 4;
    const int gt = t >> 6, cl = t & 63;
    const int row = gt * 512 + (int)rank * 64 + cl;

    // --- W_hh row into packed registers (64 x u64 = 128 floats) ---
    uint64_t w2[64];
    {
        const ulonglong2* p = (const ulonglong2*)(W_hh + (size_t)row * PROJ);
#pragma unroll
        for (int q = 0; q < 32; q++) {
            ulonglong2 v = p[q];
            w2[2 * q] = v.x;
            w2[2 * q + 1] = v.y;
        }
    }

    // ---------------- prologue phase 1: small smem loads ----------------
    float* cw = xs;           // 3072
    float* qw = xs + 3072;    // 4096
    float* bs = xs + 7168;    // 512
    for (int i = t; i < DM * 6; i += 256) cw[i] = cmdW[i];
    for (int i = t; i < DM * 8; i += 256) qw[i] = coordW[i];
    for (int i = t; i < DM; i += 256) bs[i] = cmdb[i] + coordb[i];
    for (int i = t; i < 4 * LAT; i += 256) {
        int b = i >> 8, j = i & 255;
        ctxs[i] = ctx[(size_t)(b4 + b) * LAT + j];
    }
    for (int i = t; i < PROJ * 64; i += 256) {
        int d = i >> 6, j = i & 63;
        whr[j * 128 + d] = W_hr[(size_t)d * DM + rank * 64 + j];
    }
    for (int i = t; i < 512; i += 256) hbuf[i] = 0.0f;
    __syncthreads();

    // ---------------- phase 2: fold input weights + base ----------------
    float ac[XWID];
#pragma unroll
    for (int k = 0; k < XWID; k++) ac[k] = 0.0f;
    float gB = bih[row] + bhh[row];
    {
        const float4* wr = (const float4*)(W_ih + (size_t)row * INW);
        for (int d4 = 0; d4 < DM / 4; d4++) {
            float4 w4 = wr[d4];
            float wa[4] = {w4.x, w4.y, w4.z, w4.w};
#pragma unroll
            for (int u = 0; u < 4; u++) {
                int d = d4 * 4 + u;
                float wv = wa[u];
#pragma unroll
                for (int k = 0; k < 6; k++) ac[k] += wv * cw[d * 6 + k];
#pragma unroll
                for (int k = 0; k < 8; k++) ac[6 + k] += wv * qw[d * 8 + k];
                gB += wv * bs[d];
            }
        }
    }
    {
        float bb0 = 0, bb1 = 0, bb2 = 0, bb3 = 0;
        const float4* wc = (const float4*)(W_ih + (size_t)row * INW + DM);
#pragma unroll 4
        for (int q = 0; q < LAT / 4; q++) {
            float4 w = wc[q];
            int j = q * 4;
            bb0 += w.x * ctxs[j] + w.y * ctxs[j + 1] + w.z * ctxs[j + 2] + w.w * ctxs[j + 3];
            bb1 += w.x * ctxs[256 + j] + w.y * ctxs[256 + j + 1] + w.z * ctxs[256 + j + 2] + w.w * ctxs[256 + j + 3];
            bb2 += w.x * ctxs[512 + j] + w.y * ctxs[512 + j + 1] + w.z * ctxs[512 + j + 2] + w.w * ctxs[512 + j + 3];
            bb3 += w.x * ctxs[768 + j] + w.y * ctxs[768 + j + 1] + w.z * ctxs[768 + j + 2] + w.w * ctxs[768 + j + 3];
        }
        base[t] = gB + bb0;
        base[256 + t] = gB + bb1;
        base[512 + t] = gB + bb2;
        base[768 + t] = gB + bb3;
    }
    uint64_t ac2[8];
#pragma unroll
    for (int k = 0; k < 7; k++) ac2[k] = pk(ac[2 * k], ac[2 * k + 1]);
    ac2[7] = pk(0.0f, 0.0f);
    __syncthreads();

    // ---------------- phase 3: x load (padded stride 16) ----------------
    for (int i = t; i < 4 * SS * XPAD; i += 256) {
        int b = i >> 13;
        int rem = i & 8191;
        int s = rem >> 4, k = rem & 15;
        xs[i] = (k < XWID) ? x[((size_t)(b4 + b) * SS + s) * XWID + k] : 0.0f;
    }

    // ---------------- barriers + comm addresses ----------------
    const uint32_t barF = su32(sm + SM_BARS);       // partials -> owner
    const uint32_t barH = su32(sm + SM_BARS) + 8;   // h broadcast -> all
    if (t == 0) {
        mbar_init(barF);
        mbar_init(barH);
        mbar_arm(barF, 2048);
        mbar_arm(barH, 2048);
    }

    const int bh = t >> 7, dout = t & 127;
    const uint32_t ow = (uint32_t)(dout >> 4);
    const uint32_t pa0 = mapa_rank(su32(&recv[rank * 64 + (uint32_t)bh * 16 + (dout & 15)]), ow);
    const uint32_t pa1 = mapa_rank(su32(&recv[rank * 64 + (uint32_t)(bh + 2) * 16 + (dout & 15)]), ow);
    const uint32_t pfb = mapa_rank(barF, ow);

    const int ob = t >> 4, od = t & 15;             // owner roles (t<64)
    uint32_t hdst[8], hbb[8];
    if (t < 64) {
        uint32_t la = su32(&hbuf[ob * 128 + (int)rank * 16 + od]);
#pragma unroll
        for (uint32_t d = 0; d < 8; d++) {
            hdst[d] = mapa_rank(la, d);
            hbb[d] = mapa_rank(barH, d);
        }
    }
    const int cb = t >> 6, cj = t & 63;             // c-update roles
    float c_reg = 0.0f;
    __syncthreads();
    cl_sync();

    const ulonglong2* hp0 = (const ulonglong2*)(hbuf);
    const ulonglong2* hp1 = (const ulonglong2*)(hbuf + 128);
    const ulonglong2* hp2 = (const ulonglong2*)(hbuf + 256);
    const ulonglong2* hp3 = (const ulonglong2*)(hbuf + 384);

    // =================== main sequential loop ===================
    for (int s = 0; s < SS; s++) {
        // ---- h-independent part FIRST: base + AC.x (overlaps h wait) ----
        uint64_t a0 = pk(base[t], 0.0f);
        uint64_t a1 = pk(base[256 + t], 0.0f);
        uint64_t a2 = pk(base[512 + t], 0.0f);
        uint64_t a3 = pk(base[768 + t], 0.0f);
        {
            const ulonglong2* e0 = (const ulonglong2*)(xs + 0 * 8192 + s * XPAD);
            const ulonglong2* e1 = (const ulonglong2*)(xs + 1 * 8192 + s * XPAD);
            const ulonglong2* e2 = (const ulonglong2*)(xs + 2 * 8192 + s * XPAD);
            const ulonglong2* e3 = (const ulonglong2*)(xs + 3 * 8192 + s * XPAD);
#pragma unroll
            for (int q = 0; q < 4; q++) {
                ulonglong2 u0 = e0[q], u1 = e1[q], u2 = e2[q], u3 = e3[q];
                fma2(a0, ac2[2 * q], u0.x); fma2(a0, ac2[2 * q + 1], u0.y);
                fma2(a1, ac2[2 * q], u1.x); fma2(a1, ac2[2 * q + 1], u1.y);
                fma2(a2, ac2[2 * q], u2.x); fma2(a2, ac2[2 * q + 1], u2.y);
                fma2(a3, ac2[2 * q], u3.x); fma2(a3, ac2[2 * q + 1], u3.y);
            }
        }

        // ---- wait for h[s-1] (skip at s=0: hbuf preloaded with zeros) ----
        if (s) {
            mbar_wait(barH, (uint32_t)(s - 1) & 1u);
            if (t == 0) mbar_arm(barH, 2048);
        }

        // ---- W_hh . h ----
#pragma unroll
        for (int q = 0; q < 32; q++) {
            ulonglong2 v0 = hp0[q], v1 = hp1[q], v2 = hp2[q], v3 = hp3[q];
            fma2(a0, w2[2 * q], v0.x); fma2(a0, w2[2 * q + 1], v0.y);
            fma2(a1, w2[2 * q], v1.x); fma2(a1, w2[2 * q + 1], v1.y);
            fma2(a2, w2[2 * q], v2.x); fma2(a2, w2[2 * q + 1], v2.y);
            fma2(a3, w2[2 * q], v3.x); fma2(a3, w2[2 * q + 1], v3.y);
        }
        float lo, hi, g0, g1, g2, g3;
        upk(a0, lo, hi); g0 = lo + hi;
        upk(a1, lo, hi); g1 = lo + hi;
        upk(a2, lo, hi); g2 = lo + hi;
        upk(a3, lo, hi); g3 = lo + hi;
        if (gt == 2) { g0 = ftanh(g0); g1 = ftanh(g1); g2 = ftanh(g2); g3 = ftanh(g3); }
        else         { g0 = fsig(g0);  g1 = fsig(g1);  g2 = fsig(g2);  g3 = fsig(g3);  }
        gbuf[gt * 256 + 0 * 64 + cl] = g0;
        gbuf[gt * 256 + 1 * 64 + cl] = g1;
        gbuf[gt * 256 + 2 * 64 + cl] = g2;
        gbuf[gt * 256 + 3 * 64 + cl] = g3;
        __syncthreads();

        // ---- c update: a = o * tanh(c) ----
        {
            float gi = gbuf[0 * 256 + cb * 64 + cj];
            float gf = gbuf[1 * 256 + cb * 64 + cj];
            float gg = gbuf[2 * 256 + cb * 64 + cj];
            float gO = gbuf[3 * 256 + cb * 64 + cj];
            c_reg = gf * c_reg + gi * gg;
            abuf[cb * 64 + cj] = gO * ftanh(c_reg);
        }
        __syncthreads();

        // ---- projection partials (dout, batches bh, bh+2) ----
        float pe = 0.0f, po = 0.0f;
        {
            const float4* aqe = (const float4*)(abuf + bh * 64);
            const float4* aqo = (const float4*)(abuf + (bh + 2) * 64);
#pragma unroll
            for (int q = 0; q < 16; q++) {
                int j = q * 4;
                float4 va = aqe[q];
                float4 vb = aqo[q];
                float wv0 = whr[(j + 0) * 128 + dout];
                float wv1 = whr[(j + 1) * 128 + dout];
                float wv2 = whr[(j + 2) * 128 + dout];
                float wv3 = whr[(j + 3) * 128 + dout];
                pe += va.x * wv0 + va.y * wv1 + va.z * wv2 + va.w * wv3;
                po += vb.x * wv0 + vb.y * wv1 + vb.z * wv2 + vb.w * wv3;
            }
        }
        sta32(pa0, pe, pfb);
        sta32(pa1, po, pfb);

        // ---- owners (warps 0-1): reduce 8 partials + broadcast ----
        if (t < 64) {
            mbar_wait(barF, (uint32_t)s & 1u);
            if (t == 0) mbar_arm(barF, 2048);
            float hv = recv[t] + recv[64 + t] + recv[128 + t] + recv[192 + t]
                     + recv[256 + t] + recv[320 + t] + recv[384 + t] + recv[448 + t];
#pragma unroll
            for (int d = 0; d < 8; d++) sta32(hdst[d], hv, hbb[d]);
            g_hs[((size_t)(b4 + ob) * SS + s) * PROJ + (int)rank * 16 + od] = hv;
        }
    }
    // drain the final h broadcast so no tx is pending at exit
    mbar_wait(barH, (uint32_t)(SS - 1) & 1u);
    cl_sync();
}

// =====================================================================
// Head kernel: LayerNorm + output heads. One warp per (b,s) row.
// =====================================================================
__global__ void __launch_bounds__(256)
head_kernel(const float* __restrict__ lng, const float* __restrict__ lnb,
            const float* __restrict__ ocW, const float* __restrict__ ocb,
            const float* __restrict__ oxW, const float* __restrict__ oxb,
            const float* __restrict__ scl, float* __restrict__ out)
{
    const size_t OUT_OFF = (size_t)BB * SS * NCW;
    int lane = threadIdx.x & 31;
    int row = blockIdx.x * 8 + (threadIdx.x >> 5);

    const float4 h4 = ((const float4*)g_hs)[(size_t)row * 32 + lane];
    float s = h4.x + h4.y + h4.z + h4.w;
    s = warp_sum(s);
    float mu = s * (1.0f / 128.0f);
    float dx = h4.x - mu, dy = h4.y - mu, dz = h4.z - mu, dw = h4.w - mu;
    float sq = dx * dx + dy * dy + dz * dz + dw * dw;
    sq = warp_sum(sq);
    float rs = rsqrtf(sq * (1.0f / 128.0f) + 1e-5f);

    float4 lg = ((const float4*)lng)[lane];
    float4 lb = ((const float4*)lnb)[lane];
    float y0 = dx * rs * lg.x + lb.x;
    float y1 = dy * rs * lg.y + lb.y;
    float y2 = dz * rs * lg.z + lb.z;
    float y3 = dw * rs * lg.w + lb.w;

    float l0, l1, l2, l3, l4, l5;
#define DOLOGIT(m, dst)                                                         \
    {                                                                           \
        const float* wrow = ocW + (m) * PROJ + lane * 4;                        \
        float p = y0 * wrow[0] + y1 * wrow[1] + y2 * wrow[2] + y3 * wrow[3];    \
        p = warp_sum(p);                                                        \
        dst = p + ocb[m];                                                       \
        if (lane == (m)) out[(size_t)row * NCW + (m)] = dst;                    \
    }
    DOLOGIT(0, l0) DOLOGIT(1, l1) DOLOGIT(2, l2)
    DOLOGIT(3, l3) DOLOGIT(4, l4) DOLOGIT(5, l5)
#undef DOLOGIT

    float scale = scl[0];
#define DOCOORD(m)                                                              \
    {                                                                           \
        const float* wrow = oxW + (m) * (PROJ + NCW) + lane * 4;                \
        float p = y0 * wrow[0] + y1 * wrow[1] + y2 * wrow[2] + y3 * wrow[3];    \
        p = warp_sum(p);                                                        \
        const float* wt = oxW + (m) * (PROJ + NCW) + PROJ;                      \
        float tot = p + l0 * wt[0] + l1 * wt[1] + l2 * wt[2] + l3 * wt[3]       \
                      + l4 * wt[4] + l5 * wt[5] + oxb[m];                       \
        float co = tanhf(tot * scale);                                          \
        if (lane == (m)) out[OUT_OFF + (size_t)row * NCW + (m)] = co;           \
    }
    DOCOORD(0) DOCOORD(1) DOCOORD(2) DOCOORD(3) DOCOORD(4) DOCOORD(5)
#undef DOCOORD
}

// =====================================================================
extern "C" void kernel_launch(void* const* d_in, const int* in_sizes, int n_in,
                              void* d_out, int out_size)
{
    (void)in_sizes; (void)n_in; (void)out_size;
    const float* x           = (const float*)d_in[0];
    const float* context     = (const float*)d_in[1];
    const float* cmd_W       = (const float*)d_in[2];
    const float* cmd_b       = (const float*)d_in[3];
    const float* coord_W     = (const float*)d_in[4];
    const float* coord_b     = (const float*)d_in[5];
    const float* W_ih        = (const float*)d_in[6];
    const float* W_hh        = (const float*)d_in[7];
    const float* b_ih        = (const float*)d_in[8];
    const float* b_hh        = (const float*)d_in[9];
    const float* W_hr        = (const float*)d_in[10];
    const float* ln_g        = (const float*)d_in[11];
    const float* ln_b        = (const float*)d_in[12];
    const float* outc_W      = (const float*)d_in[13];
    const float* outc_b      = (const float*)d_in[14];
    const float* outx_W      = (const float*)d_in[15];
    const float* outx_b      = (const float*)d_in[16];
    const float* coord_scale = (const float*)d_in[17];
    float* out = (float*)d_out;

    cudaFuncSetAttribute(scan_kernel,
                         cudaFuncAttributeMaxDynamicSharedMemorySize,
                         SM_TOT_BYTES);

    scan_kernel<<<128, 256, SM_TOT_BYTES>>>(x, context, cmd_W, cmd_b,
                                            coord_W, coord_b, W_ih, W_hh,
                                            b_ih, b_hh, W_hr);
    head_kernel<<<BB * SS / 8, 256>>>(ln_g, ln_b, outc_W, outc_b,
                                      outx_W, outx_b, coord_scale, out);
}